// round 1
// baseline (speedup 1.0000x reference)
#include <cuda_runtime.h>
#include <cuda_bf16.h>

// TenHotEncodeLayer: out[n, t, x[n,t,f]] = 1.0 for f in [0,10); all else 0.
// x: [32, 512, 10] int32, out: [32, 512, 5000] float32.
//
// Strategy: one CTA per (n,t) row. Each CTA streams 1250 float4 zeros
// (write-only, STG.128, memory-bound), then after a block barrier 10 threads
// overwrite the indexed positions with 1.0 (lines still L2-hot).

#define NUM_TOKENS 5000
#define ROW_F4 (NUM_TOKENS / 4)   // 1250
#define NUM_F 10
#define TPB 256

__global__ __launch_bounds__(TPB) void tenhot_kernel(
    const int* __restrict__ x, float4* __restrict__ out)
{
    const int row = blockIdx.x;
    const int tid = threadIdx.x;

    // Prefetch this thread's scatter index early (hidden under the zero fill).
    int c = 0;
    if (tid < NUM_F) c = x[row * NUM_F + tid];

    float4* o = out + (size_t)row * ROW_F4;
    const float4 z = make_float4(0.f, 0.f, 0.f, 0.f);

    // 1250 = 4*256 + 226: 4 unconditional + 1 predicated wide store.
    o[tid]        = z;
    o[tid + 256]  = z;
    o[tid + 512]  = z;
    o[tid + 768]  = z;
    if (tid + 1024 < ROW_F4) o[tid + 1024] = z;

    // Block-scope ordering: zeros performed before the 1.0 overwrites.
    __syncthreads();

    if (tid < NUM_F) {
        reinterpret_cast<float*>(o)[c] = 1.0f;
    }
}

extern "C" void kernel_launch(void* const* d_in, const int* in_sizes, int n_in,
                              void* d_out, int out_size)
{
    const int* x = (const int*)d_in[0];
    float4* out = (float4*)d_out;
    const int rows = in_sizes[0] / NUM_F;   // 32*512 = 16384
    tenhot_kernel<<<rows, TPB>>>(x, out);
}